// round 2
// baseline (speedup 1.0000x reference)
#include <cuda_runtime.h>
#include <cuda_fp16.h>
#include <cstdint>

// ---------------- problem constants ----------------
#define TOKENS   8192
#define NDIM     4096
#define KDIM     4096
#define NGROUPS  32

// ---------------- GEMM tiling ----------------
#define BM 128
#define BN 128
#define BK 64
#define STAGES 4
#define KITERS (KDIM / BK)                 // 64
#define A_STAGE_BYTES (BM * BK * 2)        // 16384
#define B_STAGE_BYTES (BN * BK * 2)        // 16384
#define STAGE_BYTES   (A_STAGE_BYTES + B_STAGE_BYTES)  // 32768
#define SMEM_TOTAL    (STAGES * STAGE_BYTES)           // 131072

// ---------------- scratch (device globals; no allocation) ----------------
__device__ uint16_t g_xh[(size_t)TOKENS * KDIM];   // 64 MB fp16
__device__ uint16_t g_wh[(size_t)NDIM * KDIM];     // 32 MB fp16

// ---------------- PTX helpers (baseline ISA only; NO tcgen05/"a" features) --
__device__ __forceinline__ uint32_t smem_to_u32(const void* p) {
    uint32_t a;
    asm("{ .reg .u64 t; cvta.to.shared.u64 t, %1; cvt.u32.u64 %0, t; }" : "=r"(a) : "l"(p));
    return a;
}

#define CP_ASYNC16(dst, src) \
    asm volatile("cp.async.cg.shared.global [%0], [%1], 16;" :: "r"(dst), "l"(src) : "memory")
#define CP_COMMIT() asm volatile("cp.async.commit_group;" ::: "memory")
#define CP_WAIT(n)  asm volatile("cp.async.wait_group %0;" :: "n"(n) : "memory")

#define LDSM4(r0, r1, r2, r3, addr) \
    asm volatile("ldmatrix.sync.aligned.m8n8.x4.shared.b16 {%0,%1,%2,%3}, [%4];" \
                 : "=r"(r0), "=r"(r1), "=r"(r2), "=r"(r3) : "r"(addr))

#define MMA16816(c, a, b0, b1) \
    asm volatile("mma.sync.aligned.m16n8k16.row.col.f32.f16.f16.f32 " \
                 "{%0,%1,%2,%3}, {%4,%5,%6,%7}, {%8,%9}, {%0,%1,%2,%3};" \
                 : "+f"((c)[0]), "+f"((c)[1]), "+f"((c)[2]), "+f"((c)[3]) \
                 : "r"((a)[0]), "r"((a)[1]), "r"((a)[2]), "r"((a)[3]), "r"(b0), "r"(b1))

// ---------------- prepass: x fp32 -> fp16 ----------------
__global__ void __launch_bounds__(256) conv_x_kernel(const float* __restrict__ x,
                                                     uint16_t* __restrict__ xh) {
    size_t i = ((size_t)blockIdx.x * 256 + threadIdx.x) * 8;
    float4 v0 = *reinterpret_cast<const float4*>(x + i);
    float4 v1 = *reinterpret_cast<const float4*>(x + i + 4);
    float vv[8] = {v0.x, v0.y, v0.z, v0.w, v1.x, v1.y, v1.z, v1.w};
    uint16_t h[8];
#pragma unroll
    for (int j = 0; j < 8; j++) h[j] = __half_as_ushort(__float2half_rn(vv[j]));
    *reinterpret_cast<uint4*>(xh + i) = *reinterpret_cast<uint4*>(h);
}

// ---------------- prepass: dequant w -> fp16 ----------------
__global__ void __launch_bounds__(256) conv_w_kernel(const int* __restrict__ q,
                                                     const float* __restrict__ s,
                                                     const float* __restrict__ z,
                                                     uint16_t* __restrict__ wh) {
    size_t i = ((size_t)blockIdx.x * 256 + threadIdx.x) * 8;
    int n = (int)(i >> 12);            // / 4096
    int k = (int)(i & 4095);
    int g = k >> 7;                    // group of 128 (8 consecutive k stay in one group)
    float sc = s[n * NGROUPS + g];
    float zz = z[n * NGROUPS + g];
    int4 q0 = *reinterpret_cast<const int4*>(q + i);
    int4 q1 = *reinterpret_cast<const int4*>(q + i + 4);
    int qq[8] = {q0.x, q0.y, q0.z, q0.w, q1.x, q1.y, q1.z, q1.w};
    uint16_t h[8];
#pragma unroll
    for (int j = 0; j < 8; j++)
        h[j] = __half_as_ushort(__float2half_rn((float)qq[j] * sc + zz));
    *reinterpret_cast<uint4*>(wh + i) = *reinterpret_cast<uint4*>(h);
}

// ---------------- GEMM: out[t,n] = sum_k xh[t,k]*wh[n,k] + bias[n] -------
// 256 threads = 8 warps in 2(m) x 4(n); warp tile 64x32.
// smem rows are 128B (64 fp16); 16B-chunk XOR swizzle (chunk ^ (row&7)) makes
// both LDGSTS stores and ldmatrix reads bank-conflict-free.
__global__ void __launch_bounds__(256, 1) gemm_kernel(const uint16_t* __restrict__ xh,
                                                      const uint16_t* __restrict__ wh,
                                                      const float* __restrict__ bias,
                                                      float* __restrict__ out) {
    extern __shared__ char smem[];
    uint32_t sbase = smem_to_u32(smem);
    int tid = threadIdx.x, lane = tid & 31, wid = tid >> 5;
    int wm = wid & 1, wn = wid >> 1;
    int m0 = blockIdx.y * BM, n0 = blockIdx.x * BN;

    // ---- loader precompute: 4 16B chunks each for A and B per stage ----
    uint32_t dstOff[4];
    const uint16_t* srcA[4];
    const uint16_t* srcB[4];
#pragma unroll
    for (int i = 0; i < 4; i++) {
        int ci = tid + i * 256;        // 0..1023
        int r = ci >> 3, c = ci & 7;   // row 0..127, chunk 0..7
        dstOff[i] = r * 128 + ((c ^ (r & 7)) << 4);
        srcA[i] = g_xh + (size_t)(m0 + r) * KDIM + c * 8;
        srcB[i] = g_wh + (size_t)(n0 + r) * KDIM + c * 8;
        (void)xh; (void)wh;
    }

    // ---- ldmatrix per-thread row bases ----
    int mBase = wm * 64 + (lane & 15);                     // + mi*16
    int aHi   = (lane >> 4) & 1;                           // k +8 selector
    int nBase = wn * 32 + (lane & 7) + ((lane & 16) ? 8 : 0);  // + p*16
    int bHi   = (lane >> 3) & 1;

    float acc[4][4][4];
#pragma unroll
    for (int mi = 0; mi < 4; mi++)
#pragma unroll
        for (int ni = 0; ni < 4; ni++)
#pragma unroll
            for (int e = 0; e < 4; e++) acc[mi][ni][e] = 0.f;

    // ---- prologue: fill STAGES-1 stages ----
#pragma unroll
    for (int st = 0; st < STAGES - 1; st++) {
        uint32_t sA = sbase + st * STAGE_BYTES;
        int kt = st * BK;
#pragma unroll
        for (int i = 0; i < 4; i++) {
            CP_ASYNC16(sA + dstOff[i], srcA[i] + kt);
            CP_ASYNC16(sA + A_STAGE_BYTES + dstOff[i], srcB[i] + kt);
        }
        CP_COMMIT();
    }

    // ---- mainloop ----
    for (int it = 0; it < KITERS; it++) {
        CP_WAIT(STAGES - 2);
        __syncthreads();

        int pf = it + STAGES - 1;
        if (pf < KITERS) {
            uint32_t sA = sbase + (pf % STAGES) * STAGE_BYTES;
            int kt = pf * BK;
#pragma unroll
            for (int i = 0; i < 4; i++) {
                CP_ASYNC16(sA + dstOff[i], srcA[i] + kt);
                CP_ASYNC16(sA + A_STAGE_BYTES + dstOff[i], srcB[i] + kt);
            }
        }
        CP_COMMIT();

        uint32_t sA = sbase + (it % STAGES) * STAGE_BYTES;
        uint32_t sB = sA + A_STAGE_BYTES;
#pragma unroll
        for (int kk = 0; kk < BK / 16; kk++) {
            uint32_t a[4][4];
#pragma unroll
            for (int mi = 0; mi < 4; mi++) {
                int row = mBase + mi * 16;
                uint32_t ad = sA + row * 128 + ((((kk << 1) | aHi) ^ (row & 7)) << 4);
                LDSM4(a[mi][0], a[mi][1], a[mi][2], a[mi][3], ad);
            }
            uint32_t b[2][4];
#pragma unroll
            for (int p = 0; p < 2; p++) {
                int row = nBase + p * 16;
                uint32_t bd = sB + row * 128 + ((((kk << 1) | bHi) ^ (row & 7)) << 4);
                LDSM4(b[p][0], b[p][1], b[p][2], b[p][3], bd);
            }
#pragma unroll
            for (int mi = 0; mi < 4; mi++)
#pragma unroll
                for (int ni = 0; ni < 4; ni++) {
                    uint32_t b0 = b[ni >> 1][(ni & 1) * 2 + 0];
                    uint32_t b1 = b[ni >> 1][(ni & 1) * 2 + 1];
                    MMA16816(acc[mi][ni], a[mi], b0, b1);
                }
        }
    }

    // ---- epilogue: direct gmem stores + bias ----
    int mB = m0 + wm * 64 + (lane >> 2);
    int nB = n0 + wn * 32 + (lane & 3) * 2;
#pragma unroll
    for (int mi = 0; mi < 4; mi++) {
#pragma unroll
        for (int ni = 0; ni < 4; ni++) {
            int m = mB + mi * 16;
            int n = nB + ni * 8;
            float b0 = __ldg(bias + n), b1 = __ldg(bias + n + 1);
            float2 v0 = {acc[mi][ni][0] + b0, acc[mi][ni][1] + b1};
            float2 v1 = {acc[mi][ni][2] + b0, acc[mi][ni][3] + b1};
            *reinterpret_cast<float2*>(out + (size_t)m * NDIM + n) = v0;
            *reinterpret_cast<float2*>(out + (size_t)(m + 8) * NDIM + n) = v1;
        }
    }
}

// ---------------- host ----------------
extern "C" void kernel_launch(void* const* d_in, const int* in_sizes, int n_in,
                              void* d_out, int out_size) {
    (void)in_sizes; (void)n_in; (void)out_size;
    const float* x    = (const float*)d_in[0];
    const int*   q    = (const int*)d_in[1];
    const float* s    = (const float*)d_in[2];
    const float* z    = (const float*)d_in[3];
    const float* bias = (const float*)d_in[4];
    float* out = (float*)d_out;

    void *p_xh, *p_wh;
    cudaGetSymbolAddress(&p_xh, g_xh);
    cudaGetSymbolAddress(&p_wh, g_wh);
    uint16_t* xh = (uint16_t*)p_xh;
    uint16_t* wh = (uint16_t*)p_wh;

    conv_x_kernel<<<(int)(((size_t)TOKENS * KDIM) / (256 * 8)), 256>>>(x, xh);
    conv_w_kernel<<<(int)(((size_t)NDIM * KDIM) / (256 * 8)), 256>>>(q, s, z, wh);

    static bool attr_set = false;
    if (!attr_set) {
        cudaFuncSetAttribute(gemm_kernel, cudaFuncAttributeMaxDynamicSharedMemorySize, SMEM_TOTAL);
        attr_set = true;
    }
    dim3 grid(NDIM / BN, TOKENS / BM);   // (32, 64), n fastest for B reuse in L2
    gemm_kernel<<<grid, 256, SMEM_TOTAL>>>(xh, wh, bias, out);
}

// round 3
// speedup vs baseline: 1.1311x; 1.1311x over previous
#include <cuda_runtime.h>
#include <cuda_fp16.h>
#include <cstdint>

// ---------------- problem constants ----------------
#define TOKENS   8192
#define NDIM     4096
#define KDIM     4096
#define NGROUPS  32

// ---------------- GEMM tiling ----------------
#define BM 128
#define BN 256
#define BK 64
#define STAGES 3
#define KITERS (KDIM / BK)                  // 64
#define A_STAGE_BYTES (BM * BK * 2)         // 16384
#define B_STAGE_BYTES (BN * BK * 2)         // 32768
#define STAGE_BYTES   (A_STAGE_BYTES + B_STAGE_BYTES)  // 49152
#define SMEM_TOTAL    (STAGES * STAGE_BYTES)           // 147456

// ---------------- scratch (device globals; no allocation) ----------------
__device__ uint16_t g_xh[(size_t)TOKENS * KDIM];   // 64 MB fp16
__device__ uint16_t g_wh[(size_t)NDIM * KDIM];     // 32 MB fp16

// ---------------- PTX helpers (baseline ISA only) ----------------
__device__ __forceinline__ uint32_t smem_to_u32(const void* p) {
    uint32_t a;
    asm("{ .reg .u64 t; cvta.to.shared.u64 t, %1; cvt.u32.u64 %0, t; }" : "=r"(a) : "l"(p));
    return a;
}

#define CP_ASYNC16(dst, src) \
    asm volatile("cp.async.cg.shared.global [%0], [%1], 16;" :: "r"(dst), "l"(src) : "memory")
#define CP_COMMIT() asm volatile("cp.async.commit_group;" ::: "memory")
#define CP_WAIT(n)  asm volatile("cp.async.wait_group %0;" :: "n"(n) : "memory")

#define LDSM4(r0, r1, r2, r3, addr) \
    asm volatile("ldmatrix.sync.aligned.m8n8.x4.shared.b16 {%0,%1,%2,%3}, [%4];" \
                 : "=r"(r0), "=r"(r1), "=r"(r2), "=r"(r3) : "r"(addr))

#define MMA16816(c, a, b0, b1) \
    asm volatile("mma.sync.aligned.m16n8k16.row.col.f32.f16.f16.f32 " \
                 "{%0,%1,%2,%3}, {%4,%5,%6,%7}, {%8,%9}, {%0,%1,%2,%3};" \
                 : "+f"((c)[0]), "+f"((c)[1]), "+f"((c)[2]), "+f"((c)[3]) \
                 : "r"((a)[0]), "r"((a)[1]), "r"((a)[2]), "r"((a)[3]), "r"(b0), "r"(b1))

// ---------------- prepass: x fp32 -> fp16 ----------------
__global__ void __launch_bounds__(256) conv_x_kernel(const float* __restrict__ x,
                                                     uint16_t* __restrict__ xh) {
    size_t i = ((size_t)blockIdx.x * 256 + threadIdx.x) * 8;
    float4 v0 = *reinterpret_cast<const float4*>(x + i);
    float4 v1 = *reinterpret_cast<const float4*>(x + i + 4);
    float vv[8] = {v0.x, v0.y, v0.z, v0.w, v1.x, v1.y, v1.z, v1.w};
    uint16_t h[8];
#pragma unroll
    for (int j = 0; j < 8; j++) h[j] = __half_as_ushort(__float2half_rn(vv[j]));
    *reinterpret_cast<uint4*>(xh + i) = *reinterpret_cast<uint4*>(h);
}

// ---------------- prepass: dequant w -> fp16 ----------------
__global__ void __launch_bounds__(256) conv_w_kernel(const int* __restrict__ q,
                                                     const float* __restrict__ s,
                                                     const float* __restrict__ z,
                                                     uint16_t* __restrict__ wh) {
    size_t i = ((size_t)blockIdx.x * 256 + threadIdx.x) * 8;
    int n = (int)(i >> 12);
    int k = (int)(i & 4095);
    int g = k >> 7;
    float sc = s[n * NGROUPS + g];
    float zz = z[n * NGROUPS + g];
    int4 q0 = *reinterpret_cast<const int4*>(q + i);
    int4 q1 = *reinterpret_cast<const int4*>(q + i + 4);
    int qq[8] = {q0.x, q0.y, q0.z, q0.w, q1.x, q1.y, q1.z, q1.w};
    uint16_t h[8];
#pragma unroll
    for (int j = 0; j < 8; j++)
        h[j] = __half_as_ushort(__float2half_rn((float)qq[j] * sc + zz));
    *reinterpret_cast<uint4*>(wh + i) = *reinterpret_cast<uint4*>(h);
}

// ---------------- GEMM: 512 threads = 16 warps, 2(m) x 8(n); warp 64x32 ---
// smem rows 128B (64 fp16), 16B-chunk XOR swizzle chunk^(row&7): bank-conflict
// free for both LDGSTS stores and ldmatrix reads.
__global__ void __launch_bounds__(512, 1) gemm_kernel(const float* __restrict__ bias,
                                                      float* __restrict__ out) {
    extern __shared__ char smem[];
    uint32_t sbase = smem_to_u32(smem);
    int tid = threadIdx.x, lane = tid & 31, wid = tid >> 5;
    int wm = wid & 1, wn = wid >> 1;                  // 2 x 8 warp grid
    int m0 = blockIdx.y * BM, n0 = blockIdx.x * BN;

    // ---- loader: 2 A-chunks + 4 B-chunks (16B each) per thread per stage ----
    uint32_t dstA[2], dstB[4];
    const uint16_t* srcA[2];
    const uint16_t* srcB[4];
#pragma unroll
    for (int i = 0; i < 2; i++) {
        int ci = tid + i * 512;          // 0..1023 (128 rows x 8 chunks)
        int r = ci >> 3, c = ci & 7;
        dstA[i] = r * 128 + ((c ^ (r & 7)) << 4);
        srcA[i] = g_xh + (size_t)(m0 + r) * KDIM + c * 8;
    }
#pragma unroll
    for (int i = 0; i < 4; i++) {
        int ci = tid + i * 512;          // 0..2047 (256 rows x 8 chunks)
        int r = ci >> 3, c = ci & 7;
        dstB[i] = A_STAGE_BYTES + r * 128 + ((c ^ (r & 7)) << 4);
        srcB[i] = g_wh + (size_t)(n0 + r) * KDIM + c * 8;
    }

    // ---- ldmatrix per-thread row bases (verified layout from R2) ----
    int mBase = wm * 64 + (lane & 15);
    int aHi   = (lane >> 4) & 1;
    int nBase = wn * 32 + (lane & 7) + ((lane & 16) ? 8 : 0);
    int bHi   = (lane >> 3) & 1;

    float acc[4][4][4];
#pragma unroll
    for (int mi = 0; mi < 4; mi++)
#pragma unroll
        for (int ni = 0; ni < 4; ni++)
#pragma unroll
            for (int e = 0; e < 4; e++) acc[mi][ni][e] = 0.f;

    // ---- prologue: fill STAGES-1 stages ----
#pragma unroll
    for (int st = 0; st < STAGES - 1; st++) {
        uint32_t sS = sbase + st * STAGE_BYTES;
        int kt = st * BK;
#pragma unroll
        for (int i = 0; i < 2; i++) CP_ASYNC16(sS + dstA[i], srcA[i] + kt);
#pragma unroll
        for (int i = 0; i < 4; i++) CP_ASYNC16(sS + dstB[i], srcB[i] + kt);
        CP_COMMIT();
    }

    // ---- mainloop ----
    for (int it = 0; it < KITERS; it++) {
        CP_WAIT(STAGES - 2);
        __syncthreads();

        int pf = it + STAGES - 1;
        if (pf < KITERS) {
            uint32_t sS = sbase + (pf % STAGES) * STAGE_BYTES;
            int kt = pf * BK;
#pragma unroll
            for (int i = 0; i < 2; i++) CP_ASYNC16(sS + dstA[i], srcA[i] + kt);
#pragma unroll
            for (int i = 0; i < 4; i++) CP_ASYNC16(sS + dstB[i], srcB[i] + kt);
        }
        CP_COMMIT();

        uint32_t sA = sbase + (it % STAGES) * STAGE_BYTES;
        uint32_t sB = sA + A_STAGE_BYTES;
#pragma unroll
        for (int kk = 0; kk < BK / 16; kk++) {
            uint32_t a[4][4];
#pragma unroll
            for (int mi = 0; mi < 4; mi++) {
                int row = mBase + mi * 16;
                uint32_t ad = sA + row * 128 + ((((kk << 1) | aHi) ^ (row & 7)) << 4);
                LDSM4(a[mi][0], a[mi][1], a[mi][2], a[mi][3], ad);
            }
            uint32_t b[2][4];
#pragma unroll
            for (int p = 0; p < 2; p++) {
                int row = nBase + p * 16;
                uint32_t bd = sB + row * 128 + ((((kk << 1) | bHi) ^ (row & 7)) << 4);
                LDSM4(b[p][0], b[p][1], b[p][2], b[p][3], bd);
            }
#pragma unroll
            for (int mi = 0; mi < 4; mi++)
#pragma unroll
                for (int ni = 0; ni < 4; ni++) {
                    uint32_t b0 = b[ni >> 1][(ni & 1) * 2 + 0];
                    uint32_t b1 = b[ni >> 1][(ni & 1) * 2 + 1];
                    MMA16816(acc[mi][ni], a[mi], b0, b1);
                }
        }
    }

    // ---- epilogue: direct gmem stores + bias ----
    int mB = m0 + wm * 64 + (lane >> 2);
    int nB = n0 + wn * 32 + (lane & 3) * 2;
#pragma unroll
    for (int mi = 0; mi < 4; mi++) {
#pragma unroll
        for (int ni = 0; ni < 4; ni++) {
            int m = mB + mi * 16;
            int n = nB + ni * 8;
            float b0 = __ldg(bias + n), b1 = __ldg(bias + n + 1);
            float2 v0 = {acc[mi][ni][0] + b0, acc[mi][ni][1] + b1};
            float2 v1 = {acc[mi][ni][2] + b0, acc[mi][ni][3] + b1};
            *reinterpret_cast<float2*>(out + (size_t)m * NDIM + n) = v0;
            *reinterpret_cast<float2*>(out + (size_t)(m + 8) * NDIM + n) = v1;
        }
    }
}

// ---------------- host ----------------
extern "C" void kernel_launch(void* const* d_in, const int* in_sizes, int n_in,
                              void* d_out, int out_size) {
    (void)in_sizes; (void)n_in; (void)out_size;
    const float* x    = (const float*)d_in[0];
    const int*   q    = (const int*)d_in[1];
    const float* s    = (const float*)d_in[2];
    const float* z    = (const float*)d_in[3];
    const float* bias = (const float*)d_in[4];
    float* out = (float*)d_out;

    void *p_xh, *p_wh;
    cudaGetSymbolAddress(&p_xh, g_xh);
    cudaGetSymbolAddress(&p_wh, g_wh);
    uint16_t* xh = (uint16_t*)p_xh;
    uint16_t* wh = (uint16_t*)p_wh;

    conv_x_kernel<<<(int)(((size_t)TOKENS * KDIM) / (256 * 8)), 256>>>(x, xh);
    conv_w_kernel<<<(int)(((size_t)NDIM * KDIM) / (256 * 8)), 256>>>(q, s, z, wh);

    static bool attr_set = false;
    if (!attr_set) {
        cudaFuncSetAttribute(gemm_kernel, cudaFuncAttributeMaxDynamicSharedMemorySize, SMEM_TOTAL);
        attr_set = true;
    }
    dim3 grid(NDIM / BN, TOKENS / BM);   // (16, 64), n fastest for B reuse in L2
    gemm_kernel<<<grid, 512, SMEM_TOTAL>>>(bias, out);
}

// round 4
// speedup vs baseline: 1.1593x; 1.0249x over previous
#include <cuda_runtime.h>
#include <cuda_fp16.h>
#include <cstdint>

// ---------------- problem constants ----------------
#define TOKENS   8192
#define NDIM     4096
#define KDIM     4096
#define NGROUPS  32

// ---------------- GEMM tiling ----------------
#define BM 128
#define BN 128
#define BK 64
#define STAGES 3
#define KITERS (KDIM / BK)                  // 64
#define A_STAGE_BYTES (BM * BK * 2)         // 16384
#define B_STAGE_BYTES (BN * BK * 2)         // 16384
#define STAGE_BYTES   (A_STAGE_BYTES + B_STAGE_BYTES)  // 32768
#define SMEM_TOTAL    (STAGES * STAGE_BYTES)           // 98304 -> 2 CTAs/SM

// ---------------- scratch (device globals; no allocation) ----------------
__device__ uint16_t g_xh[(size_t)TOKENS * KDIM];   // 64 MB fp16
__device__ uint16_t g_wh[(size_t)NDIM * KDIM];     // 32 MB fp16

// ---------------- PTX helpers (baseline ISA only) ----------------
__device__ __forceinline__ uint32_t smem_to_u32(const void* p) {
    uint32_t a;
    asm("{ .reg .u64 t; cvta.to.shared.u64 t, %1; cvt.u32.u64 %0, t; }" : "=r"(a) : "l"(p));
    return a;
}

#define CP_ASYNC16(dst, src) \
    asm volatile("cp.async.cg.shared.global [%0], [%1], 16;" :: "r"(dst), "l"(src) : "memory")
#define CP_COMMIT() asm volatile("cp.async.commit_group;" ::: "memory")
#define CP_WAIT(n)  asm volatile("cp.async.wait_group %0;" :: "n"(n) : "memory")

#define LDSM4(r0, r1, r2, r3, addr) \
    asm volatile("ldmatrix.sync.aligned.m8n8.x4.shared.b16 {%0,%1,%2,%3}, [%4];" \
                 : "=r"(r0), "=r"(r1), "=r"(r2), "=r"(r3) : "r"(addr))

#define MMA16816(c, a, b0, b1) \
    asm volatile("mma.sync.aligned.m16n8k16.row.col.f32.f16.f16.f32 " \
                 "{%0,%1,%2,%3}, {%4,%5,%6,%7}, {%8,%9}, {%0,%1,%2,%3};" \
                 : "+f"((c)[0]), "+f"((c)[1]), "+f"((c)[2]), "+f"((c)[3]) \
                 : "r"((a)[0]), "r"((a)[1]), "r"((a)[2]), "r"((a)[3]), "r"(b0), "r"(b1))

// ---------------- prepass: x fp32 -> fp16 ----------------
__global__ void __launch_bounds__(256) conv_x_kernel(const float* __restrict__ x,
                                                     uint16_t* __restrict__ xh) {
    size_t i = ((size_t)blockIdx.x * 256 + threadIdx.x) * 8;
    float4 v0 = *reinterpret_cast<const float4*>(x + i);
    float4 v1 = *reinterpret_cast<const float4*>(x + i + 4);
    float vv[8] = {v0.x, v0.y, v0.z, v0.w, v1.x, v1.y, v1.z, v1.w};
    uint16_t h[8];
#pragma unroll
    for (int j = 0; j < 8; j++) h[j] = __half_as_ushort(__float2half_rn(vv[j]));
    *reinterpret_cast<uint4*>(xh + i) = *reinterpret_cast<uint4*>(h);
}

// ---------------- prepass: dequant w -> fp16 ----------------
__global__ void __launch_bounds__(256) conv_w_kernel(const int* __restrict__ q,
                                                     const float* __restrict__ s,
                                                     const float* __restrict__ z,
                                                     uint16_t* __restrict__ wh) {
    size_t i = ((size_t)blockIdx.x * 256 + threadIdx.x) * 8;
    int n = (int)(i >> 12);
    int k = (int)(i & 4095);
    int g = k >> 7;
    float sc = s[n * NGROUPS + g];
    float zz = z[n * NGROUPS + g];
    int4 q0 = *reinterpret_cast<const int4*>(q + i);
    int4 q1 = *reinterpret_cast<const int4*>(q + i + 4);
    int qq[8] = {q0.x, q0.y, q0.z, q0.w, q1.x, q1.y, q1.z, q1.w};
    uint16_t h[8];
#pragma unroll
    for (int j = 0; j < 8; j++)
        h[j] = __half_as_ushort(__float2half_rn((float)qq[j] * sc + zz));
    *reinterpret_cast<uint4*>(wh + i) = *reinterpret_cast<uint4*>(h);
}

// ---------------- GEMM: 256 threads = 8 warps (2m x 4n), warp 64x32 ------
// 2 CTAs/SM so one CTA's barrier/pipeline bubbles are covered by the other.
// smem rows 128B (64 fp16), 16B-chunk XOR swizzle chunk^(row&7).
__global__ void __launch_bounds__(256, 2) gemm_kernel(const float* __restrict__ bias,
                                                      float* __restrict__ out) {
    extern __shared__ char smem[];
    uint32_t sbase = smem_to_u32(smem);
    int tid = threadIdx.x, lane = tid & 31, wid = tid >> 5;
    int wm = wid & 1, wn = wid >> 1;                  // 2 x 4 warp grid
    int m0 = blockIdx.y * BM, n0 = blockIdx.x * BN;

    // ---- loader bases: 4 A-chunks + 4 B-chunks (16B each) per thread ----
    // chunk i covers row r0 + 32*i, same (r&7) and c -> dst step 4096,
    // src step 32*KDIM elements.
    int r0 = tid >> 3, c0 = tid & 7;
    uint32_t dstA0 = r0 * 128 + ((c0 ^ (r0 & 7)) << 4);
    const uint16_t* srcA0 = g_xh + (size_t)(m0 + r0) * KDIM + c0 * 8;
    const uint16_t* srcB0 = g_wh + (size_t)(n0 + r0) * KDIM + c0 * 8;

    // ---- ldmatrix per-thread row bases (layout verified in R2/R3) ----
    int mBase = wm * 64 + (lane & 15);
    int aHi   = (lane >> 4) & 1;
    int nBase = wn * 32 + (lane & 7) + ((lane & 16) ? 8 : 0);
    int bHi   = (lane >> 3) & 1;

    float acc[4][4][4];
#pragma unroll
    for (int mi = 0; mi < 4; mi++)
#pragma unroll
        for (int ni = 0; ni < 4; ni++)
#pragma unroll
            for (int e = 0; e < 4; e++) acc[mi][ni][e] = 0.f;

    // ---- prologue: fill STAGES-1 stages ----
#pragma unroll
    for (int st = 0; st < STAGES - 1; st++) {
        uint32_t sS = sbase + st * STAGE_BYTES;
        int kt = st * BK;
#pragma unroll
        for (int i = 0; i < 4; i++) {
            CP_ASYNC16(sS + dstA0 + i * 4096, srcA0 + kt + (size_t)i * 32 * KDIM);
            CP_ASYNC16(sS + A_STAGE_BYTES + dstA0 + i * 4096, srcB0 + kt + (size_t)i * 32 * KDIM);
        }
        CP_COMMIT();
    }

    // ---- mainloop ----
    for (int it = 0; it < KITERS; it++) {
        CP_WAIT(STAGES - 2);
        __syncthreads();

        int pf = it + STAGES - 1;
        if (pf < KITERS) {
            uint32_t sS = sbase + (pf % STAGES) * STAGE_BYTES;
            int kt = pf * BK;
#pragma unroll
            for (int i = 0; i < 4; i++) {
                CP_ASYNC16(sS + dstA0 + i * 4096, srcA0 + kt + (size_t)i * 32 * KDIM);
                CP_ASYNC16(sS + A_STAGE_BYTES + dstA0 + i * 4096, srcB0 + kt + (size_t)i * 32 * KDIM);
            }
        }
        CP_COMMIT();

        uint32_t sA = sbase + (it % STAGES) * STAGE_BYTES;
        uint32_t sB = sA + A_STAGE_BYTES;
#pragma unroll
        for (int kk = 0; kk < BK / 16; kk++) {
            uint32_t a[4][4];
#pragma unroll
            for (int mi = 0; mi < 4; mi++) {
                int row = mBase + mi * 16;
                uint32_t ad = sA + row * 128 + ((((kk << 1) | aHi) ^ (row & 7)) << 4);
                LDSM4(a[mi][0], a[mi][1], a[mi][2], a[mi][3], ad);
            }
            uint32_t b[2][4];
#pragma unroll
            for (int p = 0; p < 2; p++) {
                int row = nBase + p * 16;
                uint32_t bd = sB + row * 128 + ((((kk << 1) | bHi) ^ (row & 7)) << 4);
                LDSM4(b[p][0], b[p][1], b[p][2], b[p][3], bd);
            }
#pragma unroll
            for (int mi = 0; mi < 4; mi++)
#pragma unroll
                for (int ni = 0; ni < 4; ni++) {
                    uint32_t b0 = b[ni >> 1][(ni & 1) * 2 + 0];
                    uint32_t b1 = b[ni >> 1][(ni & 1) * 2 + 1];
                    MMA16816(acc[mi][ni], a[mi], b0, b1);
                }
        }
    }

    // ---- epilogue: direct gmem stores + bias ----
    int mB = m0 + wm * 64 + (lane >> 2);
    int nB = n0 + wn * 32 + (lane & 3) * 2;
#pragma unroll
    for (int mi = 0; mi < 4; mi++) {
#pragma unroll
        for (int ni = 0; ni < 4; ni++) {
            int m = mB + mi * 16;
            int n = nB + ni * 8;
            float b0 = __ldg(bias + n), b1 = __ldg(bias + n + 1);
            float2 v0 = {acc[mi][ni][0] + b0, acc[mi][ni][1] + b1};
            float2 v1 = {acc[mi][ni][2] + b0, acc[mi][ni][3] + b1};
            *reinterpret_cast<float2*>(out + (size_t)m * NDIM + n) = v0;
            *reinterpret_cast<float2*>(out + (size_t)(m + 8) * NDIM + n) = v1;
        }
    }
}

// ---------------- host ----------------
extern "C" void kernel_launch(void* const* d_in, const int* in_sizes, int n_in,
                              void* d_out, int out_size) {
    (void)in_sizes; (void)n_in; (void)out_size;
    const float* x    = (const float*)d_in[0];
    const int*   q    = (const int*)d_in[1];
    const float* s    = (const float*)d_in[2];
    const float* z    = (const float*)d_in[3];
    const float* bias = (const float*)d_in[4];
    float* out = (float*)d_out;

    void *p_xh, *p_wh;
    cudaGetSymbolAddress(&p_xh, g_xh);
    cudaGetSymbolAddress(&p_wh, g_wh);
    uint16_t* xh = (uint16_t*)p_xh;
    uint16_t* wh = (uint16_t*)p_wh;

    conv_x_kernel<<<(int)(((size_t)TOKENS * KDIM) / (256 * 8)), 256>>>(x, xh);
    conv_w_kernel<<<(int)(((size_t)NDIM * KDIM) / (256 * 8)), 256>>>(q, s, z, wh);

    static bool attr_set = false;
    if (!attr_set) {
        cudaFuncSetAttribute(gemm_kernel, cudaFuncAttributeMaxDynamicSharedMemorySize, SMEM_TOTAL);
        attr_set = true;
    }
    dim3 grid(NDIM / BN, TOKENS / BM);   // (32, 64), n fastest for B reuse in L2
    gemm_kernel<<<grid, 256, SMEM_TOTAL>>>(bias, out);
}